// round 4
// baseline (speedup 1.0000x reference)
#include <cuda_runtime.h>

// LIF activation, [B=64, T=500, C=1024] fp32 -> spikes same shape.
//   kept   = Vm < 1 ? Vm : 0          (reset on threshold crossing)
//   Vm     = max(w_in*x + (1-w_l)*kept, 0)
//   spike  = Vm > 1 ? 1 : 0
// Serial over T, independent over B*C = 65536 chains.
// Scalar thread per chain (max TLP: 2048 warps) + double-buffered register
// prefetch with UNROLL=25 so prefetch distance (~400 cyc of compute) covers
// DRAM latency.

#define B_DIM 64
#define T_DIM 500
#define C_DIM 1024
#define UNROLL 25                  // timesteps per batch; 500 = 25 * 20
#define NB (T_DIM / UNROLL)        // 20 batches (even -> unroll-by-2 rotation)

__global__ __launch_bounds__(128, 16)
void lif_kernel(const float* __restrict__ x,
                const float* __restrict__ w_input_p,
                const float* __restrict__ w_leak_p,
                float* __restrict__ out)
{
    const int gid = blockIdx.x * blockDim.x + threadIdx.x;   // 0 .. B*C-1
    const int c = gid & (C_DIM - 1);
    const int b = gid >> 10;

    const float w_in = __ldg(w_input_p);
    const float omw  = 1.0f - __ldg(w_leak_p);

    const size_t base = (size_t)b * (size_t)(T_DIM * C_DIM) + c;
    const float* __restrict__ xp = x + base;
    float* __restrict__ op = out + base;

    float Vm = 0.0f;

    float bufA[UNROLL], bufB[UNROLL];

    // prime: batch 0 -> A
    #pragma unroll
    for (int u = 0; u < UNROLL; u++)
        bufA[u] = __ldcs(xp + (size_t)u * C_DIM);

    const float* pf = xp + (size_t)UNROLL * C_DIM;   // prefetch cursor

    #pragma unroll 1
    for (int batch = 0; batch < NB; batch += 2) {
        // prefetch batch+1 -> B (always exists: NB even)
        #pragma unroll
        for (int u = 0; u < UNROLL; u++)
            bufB[u] = __ldcs(pf + (size_t)u * C_DIM);
        pf += (size_t)UNROLL * C_DIM;

        // compute batch (from A)
        #pragma unroll
        for (int u = 0; u < UNROLL; u++) {
            float kept = (Vm < 1.0f) ? Vm : 0.0f;
            Vm = fmaxf(fmaf(omw, kept, w_in * bufA[u]), 0.0f);
            __stcs(op + (size_t)u * C_DIM, (Vm > 1.0f) ? 1.0f : 0.0f);
        }
        op += (size_t)UNROLL * C_DIM;

        // prefetch batch+2 -> A (last pair has none)
        if (batch + 2 < NB) {
            #pragma unroll
            for (int u = 0; u < UNROLL; u++)
                bufA[u] = __ldcs(pf + (size_t)u * C_DIM);
            pf += (size_t)UNROLL * C_DIM;
        }

        // compute batch+1 (from B)
        #pragma unroll
        for (int u = 0; u < UNROLL; u++) {
            float kept = (Vm < 1.0f) ? Vm : 0.0f;
            Vm = fmaxf(fmaf(omw, kept, w_in * bufB[u]), 0.0f);
            __stcs(op + (size_t)u * C_DIM, (Vm > 1.0f) ? 1.0f : 0.0f);
        }
        op += (size_t)UNROLL * C_DIM;
    }
}

extern "C" void kernel_launch(void* const* d_in, const int* in_sizes, int n_in,
                              void* d_out, int out_size)
{
    const float* x       = (const float*)d_in[0];
    const float* w_input = (const float*)d_in[1];
    const float* w_leak  = (const float*)d_in[2];
    float* out = (float*)d_out;

    const int total_threads = B_DIM * C_DIM;   // 65536
    const int tpb = 128;
    const int blocks = total_threads / tpb;    // 512

    lif_kernel<<<blocks, tpb>>>(x, w_input, w_leak, out);
}

// round 5
// speedup vs baseline: 3.0913x; 3.0913x over previous
#include <cuda_runtime.h>

// LIF activation, [B=64, T=500, C=1024] fp32 -> spikes same shape.
//   kept   = Vm < 1 ? Vm : 0          (reset on threshold crossing)
//   Vm     = max(w_in*x + (1-w_l)*kept, 0)
//   spike  = Vm > 1 ? 1 : 0
// Serial over T, independent over B*C = 65536 chains.
// Scalar thread per chain (2048 warps TLP) + double-buffered register
// prefetch, UNROLL=25 (~400+ cyc prefetch distance covers DRAM latency).
// NOTE: no min-blocks in launch_bounds — R4 showed a 32-reg cap spills the
// 50-float buffer to local memory and triples runtime.

#define B_DIM 64
#define T_DIM 500
#define C_DIM 1024
#define UNROLL 25                  // timesteps per batch; 500 = 25 * 20
#define NB (T_DIM / UNROLL)        // 20 batches (even -> unroll-by-2 rotation)

__global__ __launch_bounds__(128)
void lif_kernel(const float* __restrict__ x,
                const float* __restrict__ w_input_p,
                const float* __restrict__ w_leak_p,
                float* __restrict__ out)
{
    const int gid = blockIdx.x * blockDim.x + threadIdx.x;   // 0 .. B*C-1
    const int c = gid & (C_DIM - 1);
    const int b = gid >> 10;

    const float w_in = __ldg(w_input_p);
    const float omw  = 1.0f - __ldg(w_leak_p);

    const size_t base = (size_t)b * (size_t)(T_DIM * C_DIM) + c;
    const float* __restrict__ xp = x + base;
    float* __restrict__ op = out + base;

    float Vm = 0.0f;

    float bufA[UNROLL], bufB[UNROLL];

    // prime: batch 0 -> A
    #pragma unroll
    for (int u = 0; u < UNROLL; u++)
        bufA[u] = __ldcs(xp + (size_t)u * C_DIM);

    const float* pf = xp + (size_t)UNROLL * C_DIM;   // prefetch cursor

    #pragma unroll 1
    for (int batch = 0; batch < NB; batch += 2) {
        // prefetch batch+1 -> B (always exists: NB even)
        #pragma unroll
        for (int u = 0; u < UNROLL; u++)
            bufB[u] = __ldcs(pf + (size_t)u * C_DIM);
        pf += (size_t)UNROLL * C_DIM;

        // compute batch (from A)
        #pragma unroll
        for (int u = 0; u < UNROLL; u++) {
            float kept = (Vm < 1.0f) ? Vm : 0.0f;
            Vm = fmaxf(fmaf(omw, kept, w_in * bufA[u]), 0.0f);
            __stcs(op + (size_t)u * C_DIM, (Vm > 1.0f) ? 1.0f : 0.0f);
        }
        op += (size_t)UNROLL * C_DIM;

        // prefetch batch+2 -> A (last pair has none)
        if (batch + 2 < NB) {
            #pragma unroll
            for (int u = 0; u < UNROLL; u++)
                bufA[u] = __ldcs(pf + (size_t)u * C_DIM);
            pf += (size_t)UNROLL * C_DIM;
        }

        // compute batch+1 (from B)
        #pragma unroll
        for (int u = 0; u < UNROLL; u++) {
            float kept = (Vm < 1.0f) ? Vm : 0.0f;
            Vm = fmaxf(fmaf(omw, kept, w_in * bufB[u]), 0.0f);
            __stcs(op + (size_t)u * C_DIM, (Vm > 1.0f) ? 1.0f : 0.0f);
        }
        op += (size_t)UNROLL * C_DIM;
    }
}

extern "C" void kernel_launch(void* const* d_in, const int* in_sizes, int n_in,
                              void* d_out, int out_size)
{
    const float* x       = (const float*)d_in[0];
    const float* w_input = (const float*)d_in[1];
    const float* w_leak  = (const float*)d_in[2];
    float* out = (float*)d_out;

    const int total_threads = B_DIM * C_DIM;   // 65536
    const int tpb = 128;
    const int blocks = total_threads / tpb;    // 512

    lif_kernel<<<blocks, tpb>>>(x, w_input, w_leak, out);
}

// round 6
// speedup vs baseline: 3.0996x; 1.0027x over previous
#include <cuda_runtime.h>

// LIF activation, [B=64, T=500, C=1024] fp32 -> spikes same shape.
//   kept   = Vm < 1 ? Vm : 0          (reset on threshold crossing)
//   Vm     = max(w_in*x + (1-w_l)*kept, 0)
//   spike  = Vm > 1 ? 1 : 0
// Serial over T, independent over B*C = 65536 chains.
// Scalar thread per chain (2048 warps TLP) + double-buffered register
// prefetch, UNROLL=25 (~400+ cyc prefetch distance covers DRAM latency).
// 64-thread blocks -> 1024 blocks: fine-grained so per-SM block counts
// balance (7 vs 6.9 avg), removing the 4-vs-3 block tail of the 512x128 grid.
// NOTE: no min-blocks in launch_bounds — a 32-reg cap spills the 50-float
// buffer to local memory and triples runtime (R4).

#define B_DIM 64
#define T_DIM 500
#define C_DIM 1024
#define UNROLL 25                  // timesteps per batch; 500 = 25 * 20
#define NB (T_DIM / UNROLL)        // 20 batches (even -> unroll-by-2 rotation)

__global__ __launch_bounds__(64)
void lif_kernel(const float* __restrict__ x,
                const float* __restrict__ w_input_p,
                const float* __restrict__ w_leak_p,
                float* __restrict__ out)
{
    const int gid = blockIdx.x * blockDim.x + threadIdx.x;   // 0 .. B*C-1
    const int c = gid & (C_DIM - 1);
    const int b = gid >> 10;

    const float w_in = __ldg(w_input_p);
    const float omw  = 1.0f - __ldg(w_leak_p);

    const size_t base = (size_t)b * (size_t)(T_DIM * C_DIM) + c;
    const float* __restrict__ xp = x + base;
    float* __restrict__ op = out + base;

    float Vm = 0.0f;

    float bufA[UNROLL], bufB[UNROLL];

    // prime: batch 0 -> A
    #pragma unroll
    for (int u = 0; u < UNROLL; u++)
        bufA[u] = __ldcs(xp + (size_t)u * C_DIM);

    const float* pf = xp + (size_t)UNROLL * C_DIM;   // prefetch cursor

    #pragma unroll 1
    for (int batch = 0; batch < NB; batch += 2) {
        // prefetch batch+1 -> B (always exists: NB even)
        #pragma unroll
        for (int u = 0; u < UNROLL; u++)
            bufB[u] = __ldcs(pf + (size_t)u * C_DIM);
        pf += (size_t)UNROLL * C_DIM;

        // compute batch (from A)
        #pragma unroll
        for (int u = 0; u < UNROLL; u++) {
            float kept = (Vm < 1.0f) ? Vm : 0.0f;
            Vm = fmaxf(fmaf(omw, kept, w_in * bufA[u]), 0.0f);
            __stcs(op + (size_t)u * C_DIM, (Vm > 1.0f) ? 1.0f : 0.0f);
        }
        op += (size_t)UNROLL * C_DIM;

        // prefetch batch+2 -> A (last pair has none)
        if (batch + 2 < NB) {
            #pragma unroll
            for (int u = 0; u < UNROLL; u++)
                bufA[u] = __ldcs(pf + (size_t)u * C_DIM);
            pf += (size_t)UNROLL * C_DIM;
        }

        // compute batch+1 (from B)
        #pragma unroll
        for (int u = 0; u < UNROLL; u++) {
            float kept = (Vm < 1.0f) ? Vm : 0.0f;
            Vm = fmaxf(fmaf(omw, kept, w_in * bufB[u]), 0.0f);
            __stcs(op + (size_t)u * C_DIM, (Vm > 1.0f) ? 1.0f : 0.0f);
        }
        op += (size_t)UNROLL * C_DIM;
    }
}

extern "C" void kernel_launch(void* const* d_in, const int* in_sizes, int n_in,
                              void* d_out, int out_size)
{
    const float* x       = (const float*)d_in[0];
    const float* w_input = (const float*)d_in[1];
    const float* w_leak  = (const float*)d_in[2];
    float* out = (float*)d_out;

    const int total_threads = B_DIM * C_DIM;   // 65536
    const int tpb = 64;
    const int blocks = total_threads / tpb;    // 1024
    lif_kernel<<<blocks, tpb>>>(x, w_input, w_leak, out);
}